// round 12
// baseline (speedup 1.0000x reference)
#include <cuda_runtime.h>
#include <math.h>

// Shapes fixed by the problem: B=4, C=256, H=W=64, N=4096, Ci=128
#define B_  4
#define C_  256
#define N_  4096
#define CI_ 128

// Scratch (allocation-free rule: __device__ globals)
__device__ float g_xbar[B_ * C_];   // per-(b,c) spatial mean of x
__device__ float g_w[B_ * C_];      // w[b,c] = sum_k tbar[b,k] * phi_w[k,c]
__device__ float g_s[B_];           // s[b]  = sum_k tbar[b,k] * phi_b[k]

#if defined(__CUDA_ARCH__) && (__CUDA_ARCH__ >= 900)
#define PDL_TRIGGER()  cudaTriggerProgrammaticLaunchCompletion()
#define PDL_WAIT()     cudaGridDependencySynchronize()
#else
#define PDL_TRIGGER()
#define PDL_WAIT()
#endif

// ---------------------------------------------------------------------------
// Kernel 1: xbar. 512 blocks x 256 thr; 2 rows/block.
// __launch_bounds__(256,5) -> reg cap 51: enough to hold all 8 float4 loads
// (32 data regs) in flight simultaneously (MLP_eff = 8, not 2).
// ---------------------------------------------------------------------------
__global__ __launch_bounds__(256, 5) void k_rowmean(const float* __restrict__ x) {
    const int tid  = threadIdx.x;
    const int lane = tid & 31, warp = tid >> 5;
    const int row0 = blockIdx.x * 2;

    const float4* xr0 = (const float4*)(x + (size_t)row0 * N_);
    const float4* xr1 = (const float4*)(x + (size_t)(row0 + 1) * N_);

    float4 v0, v1, v2, v3, v4, v5, v6, v7;
    v0 = xr0[tid];
    v1 = xr0[tid + 256];
    v2 = xr0[tid + 512];
    v3 = xr0[tid + 768];
    v4 = xr1[tid];
    v5 = xr1[tid + 256];
    v6 = xr1[tid + 512];
    v7 = xr1[tid + 768];

    float a0 = (v0.x + v0.y) + (v0.z + v0.w)
             + (v1.x + v1.y) + (v1.z + v1.w)
             + (v2.x + v2.y) + (v2.z + v2.w)
             + (v3.x + v3.y) + (v3.z + v3.w);
    float a1 = (v4.x + v4.y) + (v4.z + v4.w)
             + (v5.x + v5.y) + (v5.z + v5.w)
             + (v6.x + v6.y) + (v6.z + v6.w)
             + (v7.x + v7.y) + (v7.z + v7.w);

    #pragma unroll
    for (int o = 16; o; o >>= 1) {
        a0 += __shfl_xor_sync(0xffffffffu, a0, o);
        a1 += __shfl_xor_sync(0xffffffffu, a1, o);
    }
    __shared__ float w0[8], w1[8];
    if (lane == 0) { w0[warp] = a0; w1[warp] = a1; }
    __syncthreads();
    if (tid == 0) {
        float s = 0.f;
        #pragma unroll
        for (int i = 0; i < 8; ++i) s += w0[i];
        g_xbar[row0] = s * (1.0f / N_);
    } else if (tid == 32) {
        float s = 0.f;
        #pragma unroll
        for (int i = 0; i < 8; ++i) s += w1[i];
        g_xbar[row0 + 1] = s * (1.0f / N_);
    }
    __syncthreads();
    PDL_TRIGGER();
}

// ---------------------------------------------------------------------------
// Kernel 2 (tiny): per batch b:
//   tbar[k] = theta_b[k] + sum_c theta_w[k,c] * xbar[b,c]
//   w[b,c]  = sum_k tbar[k] * phi_w[k,c];  s[b] = sum_k tbar[k] * phi_b[k]
// ---------------------------------------------------------------------------
__global__ __launch_bounds__(256) void k_small(const float* __restrict__ theta_w,
                                               const float* __restrict__ theta_b,
                                               const float* __restrict__ phi_w,
                                               const float* __restrict__ phi_b) {
    const int b = blockIdx.x;
    const int tid = threadIdx.x;
    const int warp = tid >> 5, lane = tid & 31;

    __shared__ float xb[C_];
    __shared__ float tb[CI_];

    // Prologue (x-independent): warm weights into L2 while rowmean drains.
    {
        const char* p = (const char*)theta_w + ((size_t)tid) * 512;
        asm volatile("prefetch.global.L2 [%0];" :: "l"(p));
        const char* q = (const char*)phi_w + ((size_t)tid) * 512;
        asm volatile("prefetch.global.L2 [%0];" :: "l"(q));
    }

    PDL_WAIT();

    xb[tid] = g_xbar[b * C_ + tid];
    __syncthreads();

    for (int i = 0; i < CI_ / 8; ++i) {
        int k = warp * (CI_ / 8) + i;
        const float* tw = theta_w + (size_t)k * C_;
        float a = 0.f;
        #pragma unroll
        for (int c = lane; c < C_; c += 32) a += tw[c] * xb[c];
        #pragma unroll
        for (int o = 16; o; o >>= 1) a += __shfl_xor_sync(0xffffffffu, a, o);
        if (lane == 0) tb[k] = a + theta_b[k];
    }
    __syncthreads();

    float wacc = 0.f;
    #pragma unroll 8
    for (int k = 0; k < CI_; ++k) wacc += tb[k] * phi_w[(size_t)k * C_ + tid];
    g_w[b * C_ + tid] = wacc;

    if (warp == 0) {
        float a = 0.f;
        #pragma unroll
        for (int k = lane; k < CI_; k += 32) a += tb[k] * phi_b[k];
        #pragma unroll
        for (int o = 16; o; o >>= 1) a += __shfl_xor_sync(0xffffffffu, a, o);
        if (lane == 0) g_s[b] = a;
    }
    __syncthreads();
    PDL_TRIGGER();
}

// ---------------------------------------------------------------------------
// Kernel 3: fused dot + sigmoid + scale, x read once into registers.
// 1024 blocks x 256 threads = (16 pixels) x (16 splits of 16 channels).
// __launch_bounds__(256,4) -> reg cap 64: all 16 xv loads batched in flight.
// ---------------------------------------------------------------------------
#define TJ_   16
#define CSPL_ 16
#define CPT_  16

__global__ __launch_bounds__(256, 4) void k_fused(const float* __restrict__ x,
                                                  float* __restrict__ out) {
    const int tid  = threadIdx.x;
    const int jloc = tid & (TJ_ - 1);
    const int csub = tid >> 4;                  // 0..15
    const int tile = blockIdx.x;                // 0..1023
    const int b    = tile >> 8;
    const int j    = (tile & 255) * TJ_ + jloc;

    __shared__ float ws[C_];
    __shared__ float part[CSPL_ * TJ_];
    __shared__ float conf_s[TJ_];
    __shared__ float sb_s;

    // Prologue: independent x loads issued before the dependency wait.
    const float* xb = x + (size_t)(b * C_) * N_ + j + (size_t)(csub * CPT_) * N_;
    float xv[CPT_];
    #pragma unroll
    for (int i = 0; i < CPT_; ++i)
        xv[i] = __ldg(xb + (size_t)i * N_);

    PDL_WAIT();

    ws[tid] = __ldcg(&g_w[b * C_ + tid]);
    if (tid == 0) sb_s = __ldcg(&g_s[b]);
    __syncthreads();

    float acc = 0.f;
    #pragma unroll
    for (int i = 0; i < CPT_; ++i) acc += ws[csub * CPT_ + i] * xv[i];
    part[csub * TJ_ + jloc] = acc;
    __syncthreads();

    if (tid < TJ_) {
        float m = 0.f;
        #pragma unroll
        for (int k = 0; k < CSPL_; ++k) m += part[k * TJ_ + tid];
        m = (m + sb_s) * (1.0f / N_);
        conf_s[tid] = 1.0f / (1.0f + expf(-m));
    }
    __syncthreads();

    const float cf = conf_s[jloc];
    float* ob = out + (size_t)(b * C_) * N_ + j + (size_t)(csub * CPT_) * N_;
    #pragma unroll
    for (int i = 0; i < CPT_; ++i)
        ob[(size_t)i * N_] = cf * xv[i];
}

// ---------------------------------------------------------------------------
extern "C" void kernel_launch(void* const* d_in, const int* in_sizes, int n_in,
                              void* d_out, int out_size) {
    const float* x       = (const float*)d_in[0];
    const float* theta_w = (const float*)d_in[1];
    const float* theta_b = (const float*)d_in[2];
    const float* phi_w   = (const float*)d_in[3];
    const float* phi_b   = (const float*)d_in[4];
    float* out = (float*)d_out;

    k_rowmean<<<B_ * C_ / 2, 256>>>(x);

    cudaLaunchAttribute pdl[1];
    pdl[0].id = cudaLaunchAttributeProgrammaticStreamSerialization;
    pdl[0].val.programmaticStreamSerializationAllowed = 1;

    {
        cudaLaunchConfig_t cfg = {};
        cfg.gridDim = dim3(B_);
        cfg.blockDim = dim3(256);
        cfg.attrs = pdl;
        cfg.numAttrs = 1;
        cudaLaunchKernelEx(&cfg, k_small, theta_w, theta_b, phi_w, phi_b);
    }
    {
        cudaLaunchConfig_t cfg = {};
        cfg.gridDim = dim3(1024);
        cfg.blockDim = dim3(256);
        cfg.attrs = pdl;
        cfg.numAttrs = 1;
        cudaLaunchKernelEx(&cfg, k_fused, x, out);
    }
}